// round 1
// baseline (speedup 1.0000x reference)
#include <cuda_runtime.h>
#include <cuda_bf16.h>

#define LSEQ   2048
#define BATCH  16
#define NIN    256
#define NCOL   3072            // BIDIR * N_OUT * K = 2*256*6
#define LANES  8192            // BATCH * BIDIR * N_OUT = 16*512
#define ELEMS  (LSEQ * LANES)  // 16,777,216
#define NCHUNK 64
#define TCHUNK 32              // LSEQ / NCHUNK

// -------- scratch (no allocs allowed -> __device__ globals) --------
// 5 planes: x1, x2, x3, f1(sigmoided), f2(sigmoided), each [t*LANES + lane]
__device__ float g_u[5][ELEMS];                 // 320 MB
__device__ float g_A1[NCHUNK * LANES];
__device__ float g_B1[NCHUNK * LANES];
__device__ float g_A2[NCHUNK * LANES];
__device__ float g_B2[NCHUNK * LANES];
__device__ float g_c1in[NCHUNK * LANES];
__device__ float g_c2in[NCHUNK * LANES];

__device__ __forceinline__ float sigmoidf_(float v) {
    return 1.0f / (1.0f + __expf(-v));
}

// ======================================================================
// GEMM: u[m][j] = sum_k x[m][k] * W[k][j];  m in [0, L*B), j in [0, 3072)
// Epilogue: j -> (dn = j/6, k = j%6); k<3 store raw, k=3/4 store sigmoid(+bias),
//           k=5 dropped. scratch index = m*512 + dn  (== t*LANES + lane)
// 128x128 block tile, BK=8, 8x8 per thread, 256 threads.
// ======================================================================
__global__ __launch_bounds__(256)
void gemm_kernel(const float* __restrict__ A,      // x  [32768, 256]
                 const float* __restrict__ Bm,     // W  [256, 3072]
                 const float* __restrict__ bias)   // [3072] viewed as [6][512]
{
    __shared__ float As[8][128];
    __shared__ float Bs[8][128];

    const int tid = threadIdx.x;
    const int bn = blockIdx.x;   // 0..23
    const int bm = blockIdx.y;   // 0..255
    const int tx = tid & 15;     // 0..15
    const int ty = tid >> 4;     // 0..15

    float acc[8][8] = {};

    const int arow = tid >> 1;          // 0..127
    const int acol = (tid & 1) * 4;     // 0 or 4
    const int brow = tid >> 5;          // 0..7
    const int bcol = (tid & 31) * 4;    // 0..124

    const float* Aptr = A + (size_t)(bm * 128 + arow) * NIN + acol;
    const float* Bptr = Bm + (size_t)brow * NCOL + bn * 128 + bcol;

    for (int kk = 0; kk < NIN; kk += 8) {
        float4 a = *(const float4*)(Aptr + kk);
        As[acol + 0][arow] = a.x;
        As[acol + 1][arow] = a.y;
        As[acol + 2][arow] = a.z;
        As[acol + 3][arow] = a.w;
        float4 b = *(const float4*)(Bptr + (size_t)kk * NCOL);
        *(float4*)&Bs[brow][bcol] = b;
        __syncthreads();

        #pragma unroll
        for (int k = 0; k < 8; k++) {
            float ra[8], rb[8];
            #pragma unroll
            for (int i = 0; i < 8; i++) ra[i] = As[k][ty * 8 + i];
            #pragma unroll
            for (int j = 0; j < 8; j++) rb[j] = Bs[k][tx * 8 + j];
            #pragma unroll
            for (int i = 0; i < 8; i++)
                #pragma unroll
                for (int j = 0; j < 8; j++)
                    acc[i][j] = fmaf(ra[i], rb[j], acc[i][j]);
        }
        __syncthreads();
    }

    // epilogue: scatter into g_u planes
    #pragma unroll
    for (int i = 0; i < 8; i++) {
        const int m = bm * 128 + ty * 8 + i;
        #pragma unroll
        for (int j = 0; j < 8; j++) {
            const int jg = bn * 128 + tx * 8 + j;
            const int k = jg % 6;
            if (k == 5) continue;                  // unused selfloop gate
            const int dn = jg / 6;                 // dir*256 + n  in [0,512)
            const size_t idx = (size_t)m * 512 + dn;
            float v = acc[i][j];
            if (k < 3) {
                g_u[k][idx] = v;
            } else {
                g_u[k][idx] = sigmoidf_(v + bias[k * 512 + dn]);
            }
        }
    }
}

// ======================================================================
// Scan pass 1: per (lane, chunk) compute affine composition over the chunk:
//   c1 -> A1*c1 + B1 ;  c2 -> A2*c2 + B2
// dir=1 lanes process time reversed (t = L-1-s).
// ======================================================================
__global__ __launch_bounds__(256)
void scan_pass1(const float* __restrict__ d_init)
{
    const int gid   = blockIdx.x * blockDim.x + threadIdx.x;
    const int lane  = gid & (LANES - 1);
    const int chunk = gid >> 13;                 // LANES = 2^13
    const int dir   = (lane >> 8) & 1;
    const int s0    = chunk * TCHUNK;

    float d;
    if (s0 == 0) {
        d = d_init[lane];
    } else {
        const int sp = s0 - 1;
        const int tp = dir ? (LSEQ - 1 - sp) : sp;
        d = g_u[1][(size_t)tp * LANES + lane];
    }

    float A1 = 1.0f, B1 = 0.0f, A2 = 1.0f, B2 = 0.0f;
    #pragma unroll 4
    for (int i = 0; i < TCHUNK; i++) {
        const int s = s0 + i;
        const int t = dir ? (LSEQ - 1 - s) : s;
        const size_t base = (size_t)t * LANES + lane;
        const float x1 = g_u[0][base];
        const float x2 = g_u[1][base];
        const float x3 = g_u[2][base];
        const float f1 = g_u[3][base];
        const float f2 = g_u[4][base];
        A1 *= f1;
        B1 = f1 * B1 + (1.0f - f1) * x1;
        const float tmp = x3 * d;
        A2 *= f2;
        B2 = f2 * B2 + (1.0f - f2) * tmp;
        d = x2;
    }

    const int o = chunk * LANES + lane;
    g_A1[o] = A1; g_B1[o] = B1;
    g_A2[o] = A2; g_B2[o] = B2;
}

// ======================================================================
// Scan pass 2: sequential combine across chunks per lane; emits chunk-initial
// carries and the final states (c1_f, c2_f, d_f) into the output tail.
// ======================================================================
__global__ __launch_bounds__(256)
void scan_pass2(const float* __restrict__ c1_init,
                const float* __restrict__ c2_init,
                float* __restrict__ out)
{
    const int lane = blockIdx.x * blockDim.x + threadIdx.x;
    float c1 = c1_init[lane];
    float c2 = c2_init[lane];

    for (int c = 0; c < NCHUNK; c++) {
        const int o = c * LANES + lane;
        g_c1in[o] = c1;
        g_c2in[o] = c2;
        c1 = g_A1[o] * c1 + g_B1[o];
        c2 = g_A2[o] * c2 + g_B2[o];
    }

    const size_t tail = (size_t)2 * LSEQ * LANES;
    out[tail + lane]             = c1;   // c1_f [B, 512]
    out[tail + LANES + lane]     = c2;   // c2_f
    const int dir = (lane >> 8) & 1;
    const int tlast = dir ? 0 : (LSEQ - 1);
    out[tail + 2 * LANES + lane] = g_u[1][(size_t)tlast * LANES + lane];  // d_f = last x2
}

// ======================================================================
// Scan pass 3: replay each chunk from its known initial carry, writing
// c1s and c2s at every step.
// ======================================================================
__global__ __launch_bounds__(256)
void scan_pass3(const float* __restrict__ d_init,
                float* __restrict__ out)
{
    const int gid   = blockIdx.x * blockDim.x + threadIdx.x;
    const int lane  = gid & (LANES - 1);
    const int chunk = gid >> 13;
    const int dir   = (lane >> 8) & 1;
    const int s0    = chunk * TCHUNK;

    float d;
    if (s0 == 0) {
        d = d_init[lane];
    } else {
        const int sp = s0 - 1;
        const int tp = dir ? (LSEQ - 1 - sp) : sp;
        d = g_u[1][(size_t)tp * LANES + lane];
    }

    const int o = chunk * LANES + lane;
    float c1 = g_c1in[o];
    float c2 = g_c2in[o];

    float* __restrict__ out_c2 = out + (size_t)LSEQ * LANES;

    #pragma unroll 4
    for (int i = 0; i < TCHUNK; i++) {
        const int s = s0 + i;
        const int t = dir ? (LSEQ - 1 - s) : s;
        const size_t base = (size_t)t * LANES + lane;
        const float x1 = g_u[0][base];
        const float x2 = g_u[1][base];
        const float x3 = g_u[2][base];
        const float f1 = g_u[3][base];
        const float f2 = g_u[4][base];
        c1 = (c1 - x1) * f1 + x1;
        const float tmp = x3 * d;
        c2 = (c2 - tmp) * f2 + tmp;
        d = x2;
        out[base]    = c1;
        out_c2[base] = c2;
    }
}

// ======================================================================
extern "C" void kernel_launch(void* const* d_in, const int* in_sizes, int n_in,
                              void* d_out, int out_size)
{
    const float* x    = (const float*)d_in[0];   // [2048,16,256]
    const float* w    = (const float*)d_in[1];   // [256,3072]
    const float* bias = (const float*)d_in[2];   // [3072]
    const float* c1i  = (const float*)d_in[3];   // [16,512]
    const float* c2i  = (const float*)d_in[4];   // [16,512]
    const float* di   = (const float*)d_in[5];   // [16,512]
    float* out = (float*)d_out;

    dim3 ggrid(NCOL / 128, (LSEQ * BATCH) / 128);   // (24, 256)
    gemm_kernel<<<ggrid, 256>>>(x, w, bias);

    scan_pass1<<<(NCHUNK * LANES) / 256, 256>>>(di);
    scan_pass2<<<LANES / 256, 256>>>(c1i, c2i, out);
    scan_pass3<<<(NCHUNK * LANES) / 256, 256>>>(di, out);
}

// round 3
// speedup vs baseline: 2.8759x; 2.8759x over previous
#include <cuda_runtime.h>
#include <cuda_bf16.h>
#include <cstdint>

#define LSEQ   2048
#define BATCH  16
#define NIN    256
#define LANES  8192
#define ELEMS  (LSEQ * LANES)
#define NCHUNK 64
#define TCHUNK 32

#define NUSED  2560              // 5 planes * 512 (k=5 dropped)
#define KEFF   768               // bf16x3: [x_hi | x_lo | x_hi]
#define NKCH   12                // KEFF / 64
#define EPI_STRIDE 132           // floats per smem row in epilogue
#define GEMM_SMEM  (128 * EPI_STRIDE * 4 > 65536 ? 128 * EPI_STRIDE * 4 : 65536)

// -------- scratch --------
__device__ float g_u[5][ELEMS];                 // x1,x2,x3,f1,f2 planes
__device__ __nv_bfloat16 g_xhi[32768 * 256];
__device__ __nv_bfloat16 g_xlo[32768 * 256];
__device__ __nv_bfloat16 g_wt[NUSED * KEFF];    // B' [n-permuted][768]
__device__ float g_A1[NCHUNK * LANES];
__device__ float g_B1[NCHUNK * LANES];
__device__ float g_A2[NCHUNK * LANES];
__device__ float g_B2[NCHUNK * LANES];
__device__ float g_c1in[NCHUNK * LANES];
__device__ float g_c2in[NCHUNK * LANES];

__device__ __forceinline__ float sigmoidf_(float v) {
    return 1.0f / (1.0f + __expf(-v));
}

// ---------------- helpers ----------------
__device__ __forceinline__ uint32_t smem_u32(const void* p) {
    uint32_t a;
    asm("{ .reg .u64 t; cvta.to.shared.u64 t, %1; cvt.u32.u64 %0, t; }" : "=r"(a) : "l"(p));
    return a;
}
__device__ __forceinline__ uint32_t swz(uint32_t b) { return b ^ ((b >> 3) & 0x70); }

__device__ __forceinline__ void cp16(uint32_t dst, const void* src) {
    asm volatile("cp.async.cg.shared.global [%0], [%1], 16;" :: "r"(dst), "l"(src) : "memory");
}
__device__ __forceinline__ void ldsm4(uint32_t* r, uint32_t addr) {
    asm volatile("ldmatrix.sync.aligned.m8n8.x4.shared.b16 {%0,%1,%2,%3}, [%4];"
                 : "=r"(r[0]), "=r"(r[1]), "=r"(r[2]), "=r"(r[3]) : "r"(addr));
}
__device__ __forceinline__ void mma16816(float* c, const uint32_t* a, const uint32_t* b) {
    asm volatile("mma.sync.aligned.m16n8k16.row.col.f32.bf16.bf16.f32 "
                 "{%0,%1,%2,%3}, {%4,%5,%6,%7}, {%8,%9}, {%0,%1,%2,%3};"
                 : "+f"(c[0]), "+f"(c[1]), "+f"(c[2]), "+f"(c[3])
                 : "r"(a[0]), "r"(a[1]), "r"(a[2]), "r"(a[3]), "r"(b[0]), "r"(b[1]));
}

// ---------------- prep kernels ----------------
__global__ __launch_bounds__(256)
void split_x(const float4* __restrict__ x)
{
    const int idx = blockIdx.x * 256 + threadIdx.x;      // 0 .. 2097151
    float4 v = x[idx];
    __nv_bfloat16 h0 = __float2bfloat16(v.x), h1 = __float2bfloat16(v.y);
    __nv_bfloat16 h2 = __float2bfloat16(v.z), h3 = __float2bfloat16(v.w);
    __nv_bfloat162* hp = (__nv_bfloat162*)g_xhi;
    __nv_bfloat162* lp = (__nv_bfloat162*)g_xlo;
    hp[idx * 2 + 0] = __nv_bfloat162(h0, h1);
    hp[idx * 2 + 1] = __nv_bfloat162(h2, h3);
    lp[idx * 2 + 0] = __nv_bfloat162(__float2bfloat16(v.x - __bfloat162float(h0)),
                                     __float2bfloat16(v.y - __bfloat162float(h1)));
    lp[idx * 2 + 1] = __nv_bfloat162(__float2bfloat16(v.z - __bfloat162float(h2)),
                                     __float2bfloat16(v.w - __bfloat162float(h3)));
}

__global__ __launch_bounds__(256)
void prep_w(const float* __restrict__ W)   // [256, 3072]
{
    const int idx = blockIdx.x * 256 + threadIdx.x;      // 0 .. 1966079
    const int p  = idx / KEFF;
    const int kk = idx - p * KEFF;
    const int dn = p & 511;
    const int kg = p >> 9;                 // 0..4
    const int jg = dn * 6 + kg;            // original column
    const int ko = kk & 255;
    float v = W[(size_t)ko * 3072 + jg];
    __nv_bfloat16 h = __float2bfloat16(v);
    g_wt[idx] = (kk >= 512) ? __float2bfloat16(v - __bfloat162float(h)) : h;
}

// ---------------- HMMA GEMM ----------------
// C[32768, 2560] = A'[32768, 768] @ B'^T (B' is [2560][768], n-major).
// Grid (20, 256): 128-col x 128-row tiles. 8 warps: warp tile 32(m) x 64(n).
__global__ __launch_bounds__(256)
void gemm_mma(const float* __restrict__ bias)
{
    extern __shared__ char smem[];
    const uint32_t sb = smem_u32(smem);
    const int tid  = threadIdx.x;
    const int warp = tid >> 5;
    const int lane = tid & 31;
    const int m0 = blockIdx.y * 128;
    const int p0 = blockIdx.x * 128;

    const int wm = warp & 3;           // 4 warp-rows
    const int wn = warp >> 2;          // 2 warp-cols
    const int rb = wm * 32;
    const int cb = wn * 64;

    // ldmatrix per-lane address components
    const int aRow  = rb + (lane & 7) + ((lane >> 3) & 1) * 8;   // + mf*16
    const int aCOff = ((lane >> 4) & 1) * 16;
    const int bRow  = cb + (lane & 7) + ((lane >> 4) & 1) * 8;   // + nf16*16
    const int bCOff = ((lane >> 3) & 1) * 16;

    float acc[2][8][4];
    #pragma unroll
    for (int i = 0; i < 2; i++)
        #pragma unroll
        for (int j = 0; j < 8; j++)
            #pragma unroll
            for (int k = 0; k < 4; k++) acc[i][j][k] = 0.0f;

    // per-thread load coordinates (4 chunks of A, 4 of B per stage)
    const int lrow = tid >> 1;            // handled via chunk math below

    auto load_stage = [&](int i, int s) {
        const int kc3 = (i & 3) << 6;
        const __nv_bfloat16* apl = (i >= 4 && i < 8) ? g_xlo : g_xhi;
        const uint32_t base = sb + (uint32_t)s * 32768u;
        #pragma unroll
        for (int j = 0; j < 4; j++) {
            const int chunk = j * 256 + tid;          // 0..1023
            const int row = chunk >> 3, c16 = chunk & 7;
            cp16(base + swz((uint32_t)(row * 128 + c16 * 16)),
                 apl + (((size_t)(m0 + row)) << 8) + kc3 + c16 * 8);
        }
        #pragma unroll
        for (int j = 0; j < 4; j++) {
            const int chunk = j * 256 + tid;
            const int row = chunk >> 3, c16 = chunk & 7;
            cp16(base + 16384u + swz((uint32_t)(row * 128 + c16 * 16)),
                 g_wt + (size_t)(p0 + row) * KEFF + (i << 6) + c16 * 8);
        }
        asm volatile("cp.async.commit_group;" ::: "memory");
    };

    load_stage(0, 0);

    for (int i = 0; i < NKCH; i++) {
        if (i + 1 < NKCH) {
            load_stage(i + 1, (i + 1) & 1);
            asm volatile("cp.async.wait_group 1;" ::: "memory");
        } else {
            asm volatile("cp.async.wait_group 0;" ::: "memory");
        }
        __syncthreads();

        const uint32_t aBase = sb + (uint32_t)(i & 1) * 32768u;
        const uint32_t bBase = aBase + 16384u;
        #pragma unroll
        for (int ks = 0; ks < 4; ks++) {
            uint32_t a[2][4];
            #pragma unroll
            for (int mf = 0; mf < 2; mf++)
                ldsm4(a[mf], aBase + swz((uint32_t)((aRow + mf * 16) * 128 + ks * 32 + aCOff)));
            uint32_t b[4][4];
            #pragma unroll
            for (int nf = 0; nf < 4; nf++)
                ldsm4(b[nf], bBase + swz((uint32_t)((bRow + nf * 16) * 128 + ks * 32 + bCOff)));
            #pragma unroll
            for (int mf = 0; mf < 2; mf++)
                #pragma unroll
                for (int n8 = 0; n8 < 8; n8++)
                    mma16816(acc[mf][n8], a[mf], &b[n8 >> 1][(n8 & 1) * 2]);
        }
        __syncthreads();
    }
    (void)lrow;

    // -------- epilogue: acc -> smem (stride-132 rows) -> g_u plane --------
    float* smf = (float*)smem;
    {
        const int r0 = rb + (lane >> 2);
        const int c0 = cb + (lane & 3) * 2;
        #pragma unroll
        for (int mf = 0; mf < 2; mf++) {
            const int r = r0 + mf * 16;
            #pragma unroll
            for (int n8 = 0; n8 < 8; n8++) {
                const int c = c0 + n8 * 8;
                *(float2*)&smf[r * EPI_STRIDE + c]       = make_float2(acc[mf][n8][0], acc[mf][n8][1]);
                *(float2*)&smf[(r + 8) * EPI_STRIDE + c] = make_float2(acc[mf][n8][2], acc[mf][n8][3]);
            }
        }
    }
    __syncthreads();

    const int kg  = p0 >> 9;          // plane index 0..4
    const int dnb = p0 & 511;
    float* plane = g_u[kg];
    const int cc = lane * 4;
    if (kg >= 3) {
        const float* bp = bias + kg * 512 + dnb;
        float4 bv = *(const float4*)(bp + cc);
        #pragma unroll
        for (int t = 0; t < 16; t++) {
            const int r = warp * 16 + t;
            float4 v = *(float4*)&smf[r * EPI_STRIDE + cc];
            v.x = sigmoidf_(v.x + bv.x);
            v.y = sigmoidf_(v.y + bv.y);
            v.z = sigmoidf_(v.z + bv.z);
            v.w = sigmoidf_(v.w + bv.w);
            *(float4*)(plane + (size_t)(m0 + r) * 512 + dnb + cc) = v;
        }
    } else {
        #pragma unroll
        for (int t = 0; t < 16; t++) {
            const int r = warp * 16 + t;
            float4 v = *(float4*)&smf[r * EPI_STRIDE + cc];
            *(float4*)(plane + (size_t)(m0 + r) * 512 + dnb + cc) = v;
        }
    }
}

// ---------------- scan ----------------
__global__ __launch_bounds__(256)
void scan_pass1(const float* __restrict__ d_init)
{
    const int gid   = blockIdx.x * blockDim.x + threadIdx.x;
    const int lane  = gid & (LANES - 1);
    const int chunk = gid >> 13;
    const int dir   = (lane >> 8) & 1;
    const int s0    = chunk * TCHUNK;

    float d;
    if (s0 == 0) d = d_init[lane];
    else {
        const int sp = s0 - 1;
        const int tp = dir ? (LSEQ - 1 - sp) : sp;
        d = g_u[1][(size_t)tp * LANES + lane];
    }

    float A1 = 1.0f, B1 = 0.0f, A2 = 1.0f, B2 = 0.0f;
    #pragma unroll 4
    for (int i = 0; i < TCHUNK; i++) {
        const int s = s0 + i;
        const int t = dir ? (LSEQ - 1 - s) : s;
        const size_t base = (size_t)t * LANES + lane;
        const float x1 = g_u[0][base];
        const float x2 = g_u[1][base];
        const float x3 = g_u[2][base];
        const float f1 = g_u[3][base];
        const float f2 = g_u[4][base];
        A1 *= f1;
        B1 = f1 * B1 + (1.0f - f1) * x1;
        const float tmp = x3 * d;
        A2 *= f2;
        B2 = f2 * B2 + (1.0f - f2) * tmp;
        d = x2;
    }
    const int o = chunk * LANES + lane;
    g_A1[o] = A1; g_B1[o] = B1;
    g_A2[o] = A2; g_B2[o] = B2;
}

__global__ __launch_bounds__(256)
void scan_pass2(const float* __restrict__ c1_init,
                const float* __restrict__ c2_init,
                float* __restrict__ out)
{
    const int lane = blockIdx.x * blockDim.x + threadIdx.x;
    float c1 = c1_init[lane];
    float c2 = c2_init[lane];
    for (int c = 0; c < NCHUNK; c++) {
        const int o = c * LANES + lane;
        g_c1in[o] = c1;
        g_c2in[o] = c2;
        c1 = g_A1[o] * c1 + g_B1[o];
        c2 = g_A2[o] * c2 + g_B2[o];
    }
    const size_t tail = (size_t)2 * LSEQ * LANES;
    out[tail + lane]         = c1;
    out[tail + LANES + lane] = c2;
    const int dir = (lane >> 8) & 1;
    const int tlast = dir ? 0 : (LSEQ - 1);
    out[tail + 2 * LANES + lane] = g_u[1][(size_t)tlast * LANES + lane];
}

__global__ __launch_bounds__(256)
void scan_pass3(const float* __restrict__ d_init,
                float* __restrict__ out)
{
    const int gid   = blockIdx.x * blockDim.x + threadIdx.x;
    const int lane  = gid & (LANES - 1);
    const int chunk = gid >> 13;
    const int dir   = (lane >> 8) & 1;
    const int s0    = chunk * TCHUNK;

    float d;
    if (s0 == 0) d = d_init[lane];
    else {
        const int sp = s0 - 1;
        const int tp = dir ? (LSEQ - 1 - sp) : sp;
        d = g_u[1][(size_t)tp * LANES + lane];
    }

    const int o = chunk * LANES + lane;
    float c1 = g_c1in[o];
    float c2 = g_c2in[o];
    float* __restrict__ out_c2 = out + (size_t)LSEQ * LANES;

    #pragma unroll 4
    for (int i = 0; i < TCHUNK; i++) {
        const int s = s0 + i;
        const int t = dir ? (LSEQ - 1 - s) : s;
        const size_t base = (size_t)t * LANES + lane;
        const float x1 = g_u[0][base];
        const float x2 = g_u[1][base];
        const float x3 = g_u[2][base];
        const float f1 = g_u[3][base];
        const float f2 = g_u[4][base];
        c1 = (c1 - x1) * f1 + x1;
        const float tmp = x3 * d;
        c2 = (c2 - tmp) * f2 + tmp;
        d = x2;
        out[base]    = c1;
        out_c2[base] = c2;
    }
}

// ======================================================================
extern "C" void kernel_launch(void* const* d_in, const int* in_sizes, int n_in,
                              void* d_out, int out_size)
{
    const float* x    = (const float*)d_in[0];
    const float* w    = (const float*)d_in[1];
    const float* bias = (const float*)d_in[2];
    const float* c1i  = (const float*)d_in[3];
    const float* c2i  = (const float*)d_in[4];
    const float* di   = (const float*)d_in[5];
    float* out = (float*)d_out;

    static int attr_set = 0;
    if (!attr_set) {
        cudaFuncSetAttribute(gemm_mma, cudaFuncAttributeMaxDynamicSharedMemorySize, GEMM_SMEM);
        attr_set = 1;
    }

    split_x<<<8192, 256>>>((const float4*)x);
    prep_w<<<7680, 256>>>(w);
    gemm_mma<<<dim3(20, 256), 256, GEMM_SMEM>>>(bias);

    scan_pass1<<<(NCHUNK * LANES) / 256, 256>>>(di);
    scan_pass2<<<LANES / 256, 256>>>(c1i, c2i, out);
    scan_pass3<<<(NCHUNK * LANES) / 256, 256>>>(di, out);
}

// round 4
// speedup vs baseline: 2.8872x; 1.0039x over previous
#include <cuda_runtime.h>
#include <cuda_bf16.h>
#include <cstdint>

#define LSEQ   2048
#define BATCH  16
#define NIN    256
#define LANES  8192
#define ELEMS  (LSEQ * LANES)
#define NCHUNK 64
#define TCHUNK 32

#define NUSED  2560              // 5 planes * 512 (k=5 dropped)
#define KEFF   768               // bf16x3: [x_hi | x_lo | x_hi]
#define NKCH   12                // KEFF / 64
#define NSTAGE 3
#define STAGE_BYTES 32768
#define EPI_STRIDE 132
#define GEMM_SMEM  (NSTAGE * STAGE_BYTES)   // 98304 >= 128*132*4 epi buffer

// -------- scratch --------
__device__ float g_u[5][ELEMS];
__device__ __nv_bfloat16 g_xhi[32768 * 256];
__device__ __nv_bfloat16 g_xlo[32768 * 256];
__device__ __nv_bfloat16 g_wt[NUSED * KEFF];
__device__ float g_A1[NCHUNK * LANES];
__device__ float g_B1[NCHUNK * LANES];
__device__ float g_A2[NCHUNK * LANES];
__device__ float g_B2[NCHUNK * LANES];
__device__ float g_c1in[NCHUNK * LANES];
__device__ float g_c2in[NCHUNK * LANES];

__device__ __forceinline__ float sigmoidf_(float v) {
    return 1.0f / (1.0f + __expf(-v));
}

// ---------------- helpers ----------------
__device__ __forceinline__ uint32_t smem_u32(const void* p) {
    uint32_t a;
    asm("{ .reg .u64 t; cvta.to.shared.u64 t, %1; cvt.u32.u64 %0, t; }" : "=r"(a) : "l"(p));
    return a;
}
__device__ __forceinline__ uint32_t swz(uint32_t b) { return b ^ ((b >> 3) & 0x70); }

__device__ __forceinline__ void cp16(uint32_t dst, const void* src) {
    asm volatile("cp.async.cg.shared.global [%0], [%1], 16;" :: "r"(dst), "l"(src) : "memory");
}
__device__ __forceinline__ void ldsm4(uint32_t* r, uint32_t addr) {
    asm volatile("ldmatrix.sync.aligned.m8n8.x4.shared.b16 {%0,%1,%2,%3}, [%4];"
                 : "=r"(r[0]), "=r"(r[1]), "=r"(r[2]), "=r"(r[3]) : "r"(addr));
}
__device__ __forceinline__ void mma16816(float* c, const uint32_t* a, const uint32_t* b) {
    asm volatile("mma.sync.aligned.m16n8k16.row.col.f32.bf16.bf16.f32 "
                 "{%0,%1,%2,%3}, {%4,%5,%6,%7}, {%8,%9}, {%0,%1,%2,%3};"
                 : "+f"(c[0]), "+f"(c[1]), "+f"(c[2]), "+f"(c[3])
                 : "r"(a[0]), "r"(a[1]), "r"(a[2]), "r"(a[3]), "r"(b[0]), "r"(b[1]));
}

// ---------------- prep kernels ----------------
__global__ __launch_bounds__(256)
void split_x(const float4* __restrict__ x)
{
    const int idx = blockIdx.x * 256 + threadIdx.x;
    float4 v = x[idx];
    __nv_bfloat16 h0 = __float2bfloat16(v.x), h1 = __float2bfloat16(v.y);
    __nv_bfloat16 h2 = __float2bfloat16(v.z), h3 = __float2bfloat16(v.w);
    __nv_bfloat162* hp = (__nv_bfloat162*)g_xhi;
    __nv_bfloat162* lp = (__nv_bfloat162*)g_xlo;
    hp[idx * 2 + 0] = __nv_bfloat162(h0, h1);
    hp[idx * 2 + 1] = __nv_bfloat162(h2, h3);
    lp[idx * 2 + 0] = __nv_bfloat162(__float2bfloat16(v.x - __bfloat162float(h0)),
                                     __float2bfloat16(v.y - __bfloat162float(h1)));
    lp[idx * 2 + 1] = __nv_bfloat162(__float2bfloat16(v.z - __bfloat162float(h2)),
                                     __float2bfloat16(v.w - __bfloat162float(h3)));
}

__global__ __launch_bounds__(256)
void prep_w(const float* __restrict__ W)   // [256, 3072]
{
    const int idx = blockIdx.x * 256 + threadIdx.x;
    const int p  = idx / KEFF;
    const int kk = idx - p * KEFF;
    const int dn = p & 511;
    const int kg = p >> 9;
    const int jg = dn * 6 + kg;
    const int ko = kk & 255;
    float v = W[(size_t)ko * 3072 + jg];
    __nv_bfloat16 h = __float2bfloat16(v);
    g_wt[idx] = (kk >= 512) ? __float2bfloat16(v - __bfloat162float(h)) : h;
}

// ---------------- HMMA GEMM, 3-stage pipeline + ks-level frag prefetch ----
// C[32768, 2560] = A'[32768, 768] @ B'^T.  Grid (20, 256); CTA 128x128;
// 8 warps (4x2), warp tile 32m x 64n; K chunks of 64, NSTAGE=3.
__global__ __launch_bounds__(256)
void gemm_mma(const float* __restrict__ bias)
{
    extern __shared__ char smem[];
    const uint32_t sb = smem_u32(smem);
    const int tid  = threadIdx.x;
    const int warp = tid >> 5;
    const int lane = tid & 31;
    const int m0 = blockIdx.y * 128;
    const int p0 = blockIdx.x * 128;

    const int wm = warp & 3;
    const int wn = warp >> 2;
    const int rb = wm * 32;
    const int cb = wn * 64;

    const int aRow  = rb + (lane & 7) + ((lane >> 3) & 1) * 8;
    const int aCOff = ((lane >> 4) & 1) * 16;
    const int bRow  = cb + (lane & 7) + ((lane >> 4) & 1) * 8;
    const int bCOff = ((lane >> 3) & 1) * 16;

    float acc[2][8][4];
    #pragma unroll
    for (int i = 0; i < 2; i++)
        #pragma unroll
        for (int j = 0; j < 8; j++)
            #pragma unroll
            for (int k = 0; k < 4; k++) acc[i][j][k] = 0.0f;

    // per-thread cp.async coordinates (same for every stage)
    const int lr  = tid >> 3;          // row 0..31 base (A: +j*32), col16 = tid&7
    const int lc16 = tid & 7;

    #define LOAD_STAGE(i, s)                                                            \
    do {                                                                                \
        const int kc3_ = ((i) & 3) << 6;                                                \
        const __nv_bfloat16* apl_ = ((i) >= 4 && (i) < 8) ? g_xlo : g_xhi;              \
        const uint32_t base_ = sb + (uint32_t)(s) * STAGE_BYTES;                        \
        _Pragma("unroll")                                                               \
        for (int j = 0; j < 4; j++) {                                                   \
            const int row_ = lr + j * 32;                                               \
            cp16(base_ + swz((uint32_t)(row_ * 128 + lc16 * 16)),                       \
                 apl_ + (((size_t)(m0 + row_)) << 8) + kc3_ + lc16 * 8);                \
        }                                                                               \
        _Pragma("unroll")                                                               \
        for (int j = 0; j < 4; j++) {                                                   \
            const int row_ = lr + j * 32;                                               \
            cp16(base_ + 16384u + swz((uint32_t)(row_ * 128 + lc16 * 16)),              \
                 g_wt + (size_t)(p0 + row_) * KEFF + ((i) << 6) + lc16 * 8);            \
        }                                                                               \
        asm volatile("cp.async.commit_group;" ::: "memory");                            \
    } while (0)

    LOAD_STAGE(0, 0);
    LOAD_STAGE(1, 1);

    int stage = 0;
    for (int i = 0; i < NKCH; i++) {
        asm volatile("cp.async.wait_group 1;" ::: "memory");
        __syncthreads();

        if (i + 2 < NKCH) {
            const int s2 = (stage + 2 >= NSTAGE) ? (stage + 2 - NSTAGE) : (stage + 2);
            LOAD_STAGE(i + 2, s2);
        }

        const uint32_t aBase = sb + (uint32_t)stage * STAGE_BYTES;
        const uint32_t bBase = aBase + 16384u;

        uint32_t afr[2][2][4];
        uint32_t bfr[2][4][4];
        // prefetch ks=0 frags
        #pragma unroll
        for (int mf = 0; mf < 2; mf++)
            ldsm4(afr[0][mf], aBase + swz((uint32_t)((aRow + mf * 16) * 128 + aCOff)));
        #pragma unroll
        for (int nf = 0; nf < 4; nf++)
            ldsm4(bfr[0][nf], bBase + swz((uint32_t)((bRow + nf * 16) * 128 + bCOff)));

        #pragma unroll
        for (int ks = 0; ks < 4; ks++) {
            const int cur = ks & 1, nxt = cur ^ 1;
            if (ks < 3) {
                const uint32_t co = (uint32_t)((ks + 1) * 32);
                #pragma unroll
                for (int mf = 0; mf < 2; mf++)
                    ldsm4(afr[nxt][mf], aBase + swz((uint32_t)((aRow + mf * 16) * 128) + co + aCOff));
                #pragma unroll
                for (int nf = 0; nf < 4; nf++)
                    ldsm4(bfr[nxt][nf], bBase + swz((uint32_t)((bRow + nf * 16) * 128) + co + bCOff));
            }
            #pragma unroll
            for (int mf = 0; mf < 2; mf++)
                #pragma unroll
                for (int n8 = 0; n8 < 8; n8++)
                    mma16816(acc[mf][n8], afr[cur][mf], &bfr[cur][n8 >> 1][(n8 & 1) * 2]);
        }

        stage = (stage + 1 >= NSTAGE) ? 0 : stage + 1;
    }
    #undef LOAD_STAGE

    __syncthreads();   // all MMAs done before smem reuse

    // -------- epilogue: acc -> smem (stride-132) -> g_u plane --------
    float* smf = (float*)smem;
    {
        const int r0 = rb + (lane >> 2);
        const int c0 = cb + (lane & 3) * 2;
        #pragma unroll
        for (int mf = 0; mf < 2; mf++) {
            const int r = r0 + mf * 16;
            #pragma unroll
            for (int n8 = 0; n8 < 8; n8++) {
                const int c = c0 + n8 * 8;
                *(float2*)&smf[r * EPI_STRIDE + c]       = make_float2(acc[mf][n8][0], acc[mf][n8][1]);
                *(float2*)&smf[(r + 8) * EPI_STRIDE + c] = make_float2(acc[mf][n8][2], acc[mf][n8][3]);
            }
        }
    }
    __syncthreads();

    const int kg  = p0 >> 9;
    const int dnb = p0 & 511;
    float* plane = g_u[kg];
    const int cc = lane * 4;
    if (kg >= 3) {
        const float* bp = bias + kg * 512 + dnb;
        float4 bv = *(const float4*)(bp + cc);
        #pragma unroll
        for (int t = 0; t < 16; t++) {
            const int r = warp * 16 + t;
            float4 v = *(float4*)&smf[r * EPI_STRIDE + cc];
            v.x = sigmoidf_(v.x + bv.x);
            v.y = sigmoidf_(v.y + bv.y);
            v.z = sigmoidf_(v.z + bv.z);
            v.w = sigmoidf_(v.w + bv.w);
            *(float4*)(plane + (size_t)(m0 + r) * 512 + dnb + cc) = v;
        }
    } else {
        #pragma unroll
        for (int t = 0; t < 16; t++) {
            const int r = warp * 16 + t;
            float4 v = *(float4*)&smf[r * EPI_STRIDE + cc];
            *(float4*)(plane + (size_t)(m0 + r) * 512 + dnb + cc) = v;
        }
    }
}

// ---------------- scan ----------------
__global__ __launch_bounds__(256)
void scan_pass1(const float* __restrict__ d_init)
{
    const int gid   = blockIdx.x * blockDim.x + threadIdx.x;
    const int lane  = gid & (LANES - 1);
    const int chunk = gid >> 13;
    const int dir   = (lane >> 8) & 1;
    const int s0    = chunk * TCHUNK;

    float d;
    if (s0 == 0) d = d_init[lane];
    else {
        const int sp = s0 - 1;
        const int tp = dir ? (LSEQ - 1 - sp) : sp;
        d = g_u[1][(size_t)tp * LANES + lane];
    }

    float A1 = 1.0f, B1 = 0.0f, A2 = 1.0f, B2 = 0.0f;
    #pragma unroll 4
    for (int i = 0; i < TCHUNK; i++) {
        const int s = s0 + i;
        const int t = dir ? (LSEQ - 1 - s) : s;
        const size_t base = (size_t)t * LANES + lane;
        const float x1 = g_u[0][base];
        const float x2 = g_u[1][base];
        const float x3 = g_u[2][base];
        const float f1 = g_u[3][base];
        const float f2 = g_u[4][base];
        A1 *= f1;
        B1 = f1 * B1 + (1.0f - f1) * x1;
        const float tmp = x3 * d;
        A2 *= f2;
        B2 = f2 * B2 + (1.0f - f2) * tmp;
        d = x2;
    }
    const int o = chunk * LANES + lane;
    g_A1[o] = A1; g_B1[o] = B1;
    g_A2[o] = A2; g_B2[o] = B2;
}

__global__ __launch_bounds__(256)
void scan_pass2(const float* __restrict__ c1_init,
                const float* __restrict__ c2_init,
                float* __restrict__ out)
{
    const int lane = blockIdx.x * blockDim.x + threadIdx.x;
    float c1 = c1_init[lane];
    float c2 = c2_init[lane];
    for (int c = 0; c < NCHUNK; c++) {
        const int o = c * LANES + lane;
        g_c1in[o] = c1;
        g_c2in[o] = c2;
        c1 = g_A1[o] * c1 + g_B1[o];
        c2 = g_A2[o] * c2 + g_B2[o];
    }
    const size_t tail = (size_t)2 * LSEQ * LANES;
    out[tail + lane]         = c1;
    out[tail + LANES + lane] = c2;
    const int dir = (lane >> 8) & 1;
    const int tlast = dir ? 0 : (LSEQ - 1);
    out[tail + 2 * LANES + lane] = g_u[1][(size_t)tlast * LANES + lane];
}

__global__ __launch_bounds__(256)
void scan_pass3(const float* __restrict__ d_init,
                float* __restrict__ out)
{
    const int gid   = blockIdx.x * blockDim.x + threadIdx.x;
    const int lane  = gid & (LANES - 1);
    const int chunk = gid >> 13;
    const int dir   = (lane >> 8) & 1;
    const int s0    = chunk * TCHUNK;

    float d;
    if (s0 == 0) d = d_init[lane];
    else {
        const int sp = s0 - 1;
        const int tp = dir ? (LSEQ - 1 - sp) : sp;
        d = g_u[1][(size_t)tp * LANES + lane];
    }

    const int o = chunk * LANES + lane;
    float c1 = g_c1in[o];
    float c2 = g_c2in[o];
    float* __restrict__ out_c2 = out + (size_t)LSEQ * LANES;

    #pragma unroll 4
    for (int i = 0; i < TCHUNK; i++) {
        const int s = s0 + i;
        const int t = dir ? (LSEQ - 1 - s) : s;
        const size_t base = (size_t)t * LANES + lane;
        const float x1 = g_u[0][base];
        const float x2 = g_u[1][base];
        const float x3 = g_u[2][base];
        const float f1 = g_u[3][base];
        const float f2 = g_u[4][base];
        c1 = (c1 - x1) * f1 + x1;
        const float tmp = x3 * d;
        c2 = (c2 - tmp) * f2 + tmp;
        d = x2;
        out[base]    = c1;
        out_c2[base] = c2;
    }
}

// ======================================================================
extern "C" void kernel_launch(void* const* d_in, const int* in_sizes, int n_in,
                              void* d_out, int out_size)
{
    const float* x    = (const float*)d_in[0];
    const float* w    = (const float*)d_in[1];
    const float* bias = (const float*)d_in[2];
    const float* c1i  = (const float*)d_in[3];
    const float* c2i  = (const float*)d_in[4];
    const float* di   = (const float*)d_in[5];
    float* out = (float*)d_out;

    static int attr_set = 0;
    if (!attr_set) {
        cudaFuncSetAttribute(gemm_mma, cudaFuncAttributeMaxDynamicSharedMemorySize, GEMM_SMEM);
        attr_set = 1;
    }

    split_x<<<8192, 256>>>((const float4*)x);
    prep_w<<<7680, 256>>>(w);
    gemm_mma<<<dim3(20, 256), 256, GEMM_SMEM>>>(bias);

    scan_pass1<<<(NCHUNK * LANES) / 256, 256>>>(di);
    scan_pass2<<<LANES / 256, 256>>>(c1i, c2i, out);
    scan_pass3<<<(NCHUNK * LANES) / 256, 256>>>(di, out);
}

// round 5
// speedup vs baseline: 3.3783x; 1.1701x over previous
#include <cuda_runtime.h>
#include <cuda_bf16.h>
#include <cuda_fp16.h>
#include <cstdint>

#define LSEQ   2048
#define BATCH  16
#define NIN    256
#define LANES  8192
#define LANE2  4096
#define ELEMS  (LSEQ * LANES)
#define NCHUNK 64
#define TCHUNK 32

#define NUSED  2560
#define KEFF   768               // bf16x3: [x_hi | x_lo | x_hi]
#define NKCH   12
#define NSTAGE 3
#define STAGE_BYTES 32768
#define EPI_STRIDE 132
#define GEMM_SMEM  (NSTAGE * STAGE_BYTES)

// -------- scratch --------
__device__ __half g_u[5][ELEMS];                // fp16 planes: x1,x2,x3,f1,f2 (160MB)
__device__ __nv_bfloat16 g_xhi[32768 * 256];
__device__ __nv_bfloat16 g_xlo[32768 * 256];
__device__ __nv_bfloat16 g_wt[NUSED * KEFF];
__device__ float g_A1[NCHUNK * LANES];
__device__ float g_B1[NCHUNK * LANES];
__device__ float g_A2[NCHUNK * LANES];
__device__ float g_B2[NCHUNK * LANES];
__device__ float g_c1in[NCHUNK * LANES];
__device__ float g_c2in[NCHUNK * LANES];

__device__ __forceinline__ float sigmoidf_(float v) {
    return 1.0f / (1.0f + __expf(-v));
}

// ---------------- helpers ----------------
__device__ __forceinline__ uint32_t smem_u32(const void* p) {
    uint32_t a;
    asm("{ .reg .u64 t; cvta.to.shared.u64 t, %1; cvt.u32.u64 %0, t; }" : "=r"(a) : "l"(p));
    return a;
}
__device__ __forceinline__ uint32_t swz(uint32_t b) { return b ^ ((b >> 3) & 0x70); }

__device__ __forceinline__ void cp16(uint32_t dst, const void* src) {
    asm volatile("cp.async.cg.shared.global [%0], [%1], 16;" :: "r"(dst), "l"(src) : "memory");
}
__device__ __forceinline__ void ldsm4(uint32_t* r, uint32_t addr) {
    asm volatile("ldmatrix.sync.aligned.m8n8.x4.shared.b16 {%0,%1,%2,%3}, [%4];"
                 : "=r"(r[0]), "=r"(r[1]), "=r"(r[2]), "=r"(r[3]) : "r"(addr));
}
__device__ __forceinline__ void mma16816(float* c, const uint32_t* a, const uint32_t* b) {
    asm volatile("mma.sync.aligned.m16n8k16.row.col.f32.bf16.bf16.f32 "
                 "{%0,%1,%2,%3}, {%4,%5,%6,%7}, {%8,%9}, {%0,%1,%2,%3};"
                 : "+f"(c[0]), "+f"(c[1]), "+f"(c[2]), "+f"(c[3])
                 : "r"(a[0]), "r"(a[1]), "r"(a[2]), "r"(a[3]), "r"(b[0]), "r"(b[1]));
}

// ---------------- prep kernels ----------------
__global__ __launch_bounds__(256)
void split_x(const float4* __restrict__ x)
{
    const int idx = blockIdx.x * 256 + threadIdx.x;
    float4 v = x[idx];
    __nv_bfloat16 h0 = __float2bfloat16(v.x), h1 = __float2bfloat16(v.y);
    __nv_bfloat16 h2 = __float2bfloat16(v.z), h3 = __float2bfloat16(v.w);
    __nv_bfloat162* hp = (__nv_bfloat162*)g_xhi;
    __nv_bfloat162* lp = (__nv_bfloat162*)g_xlo;
    hp[idx * 2 + 0] = __nv_bfloat162(h0, h1);
    hp[idx * 2 + 1] = __nv_bfloat162(h2, h3);
    lp[idx * 2 + 0] = __nv_bfloat162(__float2bfloat16(v.x - __bfloat162float(h0)),
                                     __float2bfloat16(v.y - __bfloat162float(h1)));
    lp[idx * 2 + 1] = __nv_bfloat162(__float2bfloat16(v.z - __bfloat162float(h2)),
                                     __float2bfloat16(v.w - __bfloat162float(h3)));
}

__global__ __launch_bounds__(256)
void prep_w(const float* __restrict__ W)
{
    const int idx = blockIdx.x * 256 + threadIdx.x;
    const int p  = idx / KEFF;
    const int kk = idx - p * KEFF;
    const int dn = p & 511;
    const int kg = p >> 9;
    const int jg = dn * 6 + kg;
    const int ko = kk & 255;
    float v = W[(size_t)ko * 3072 + jg];
    __nv_bfloat16 h = __float2bfloat16(v);
    g_wt[idx] = (kk >= 512) ? __float2bfloat16(v - __bfloat162float(h)) : h;
}

// ---------------- HMMA GEMM (R4 mainloop, fp16 epilogue) ----------------
__global__ __launch_bounds__(256)
void gemm_mma(const float* __restrict__ bias)
{
    extern __shared__ char smem[];
    const uint32_t sb = smem_u32(smem);
    const int tid  = threadIdx.x;
    const int warp = tid >> 5;
    const int lane = tid & 31;
    const int m0 = blockIdx.y * 128;
    const int p0 = blockIdx.x * 128;

    const int wm = warp & 3;
    const int wn = warp >> 2;
    const int rb = wm * 32;
    const int cb = wn * 64;

    const int aRow  = rb + (lane & 7) + ((lane >> 3) & 1) * 8;
    const int aCOff = ((lane >> 4) & 1) * 16;
    const int bRow  = cb + (lane & 7) + ((lane >> 4) & 1) * 8;
    const int bCOff = ((lane >> 3) & 1) * 16;

    float acc[2][8][4];
    #pragma unroll
    for (int i = 0; i < 2; i++)
        #pragma unroll
        for (int j = 0; j < 8; j++)
            #pragma unroll
            for (int k = 0; k < 4; k++) acc[i][j][k] = 0.0f;

    const int lr   = tid >> 3;
    const int lc16 = tid & 7;

    #define LOAD_STAGE(i, s)                                                            \
    do {                                                                                \
        const int kc3_ = ((i) & 3) << 6;                                                \
        const __nv_bfloat16* apl_ = ((i) >= 4 && (i) < 8) ? g_xlo : g_xhi;              \
        const uint32_t base_ = sb + (uint32_t)(s) * STAGE_BYTES;                        \
        _Pragma("unroll")                                                               \
        for (int j = 0; j < 4; j++) {                                                   \
            const int row_ = lr + j * 32;                                               \
            cp16(base_ + swz((uint32_t)(row_ * 128 + lc16 * 16)),                       \
                 apl_ + (((size_t)(m0 + row_)) << 8) + kc3_ + lc16 * 8);                \
        }                                                                               \
        _Pragma("unroll")                                                               \
        for (int j = 0; j < 4; j++) {                                                   \
            const int row_ = lr + j * 32;                                               \
            cp16(base_ + 16384u + swz((uint32_t)(row_ * 128 + lc16 * 16)),              \
                 g_wt + (size_t)(p0 + row_) * KEFF + ((i) << 6) + lc16 * 8);            \
        }                                                                               \
        asm volatile("cp.async.commit_group;" ::: "memory");                            \
    } while (0)

    LOAD_STAGE(0, 0);
    LOAD_STAGE(1, 1);

    int stage = 0;
    for (int i = 0; i < NKCH; i++) {
        asm volatile("cp.async.wait_group 1;" ::: "memory");
        __syncthreads();

        if (i + 2 < NKCH) {
            const int s2 = (stage + 2 >= NSTAGE) ? (stage + 2 - NSTAGE) : (stage + 2);
            LOAD_STAGE(i + 2, s2);
        }

        const uint32_t aBase = sb + (uint32_t)stage * STAGE_BYTES;
        const uint32_t bBase = aBase + 16384u;

        uint32_t afr[2][2][4];
        uint32_t bfr[2][4][4];
        #pragma unroll
        for (int mf = 0; mf < 2; mf++)
            ldsm4(afr[0][mf], aBase + swz((uint32_t)((aRow + mf * 16) * 128 + aCOff)));
        #pragma unroll
        for (int nf = 0; nf < 4; nf++)
            ldsm4(bfr[0][nf], bBase + swz((uint32_t)((bRow + nf * 16) * 128 + bCOff)));

        #pragma unroll
        for (int ks = 0; ks < 4; ks++) {
            const int cur = ks & 1, nxt = cur ^ 1;
            if (ks < 3) {
                const uint32_t co = (uint32_t)((ks + 1) * 32);
                #pragma unroll
                for (int mf = 0; mf < 2; mf++)
                    ldsm4(afr[nxt][mf], aBase + swz((uint32_t)((aRow + mf * 16) * 128) + co + aCOff));
                #pragma unroll
                for (int nf = 0; nf < 4; nf++)
                    ldsm4(bfr[nxt][nf], bBase + swz((uint32_t)((bRow + nf * 16) * 128) + co + bCOff));
            }
            #pragma unroll
            for (int mf = 0; mf < 2; mf++)
                #pragma unroll
                for (int n8 = 0; n8 < 8; n8++)
                    mma16816(acc[mf][n8], afr[cur][mf], &bfr[cur][n8 >> 1][(n8 & 1) * 2]);
        }

        stage = (stage + 1 >= NSTAGE) ? 0 : stage + 1;
    }
    #undef LOAD_STAGE

    __syncthreads();

    // -------- epilogue: acc -> smem (fp32) -> fp16 g_u plane --------
    float* smf = (float*)smem;
    {
        const int r0 = rb + (lane >> 2);
        const int c0 = cb + (lane & 3) * 2;
        #pragma unroll
        for (int mf = 0; mf < 2; mf++) {
            const int r = r0 + mf * 16;
            #pragma unroll
            for (int n8 = 0; n8 < 8; n8++) {
                const int c = c0 + n8 * 8;
                *(float2*)&smf[r * EPI_STRIDE + c]       = make_float2(acc[mf][n8][0], acc[mf][n8][1]);
                *(float2*)&smf[(r + 8) * EPI_STRIDE + c] = make_float2(acc[mf][n8][2], acc[mf][n8][3]);
            }
        }
    }
    __syncthreads();

    const int kg  = p0 >> 9;
    const int dnb = p0 & 511;
    __half* plane = g_u[kg];
    const int cc = lane * 4;
    if (kg >= 3) {
        const float* bp = bias + kg * 512 + dnb;
        float4 bv = *(const float4*)(bp + cc);
        #pragma unroll
        for (int t = 0; t < 16; t++) {
            const int r = warp * 16 + t;
            float4 v = *(float4*)&smf[r * EPI_STRIDE + cc];
            __half2 p0h = __floats2half2_rn(sigmoidf_(v.x + bv.x), sigmoidf_(v.y + bv.y));
            __half2 p1h = __floats2half2_rn(sigmoidf_(v.z + bv.z), sigmoidf_(v.w + bv.w));
            uint2 u2;
            u2.x = *(unsigned*)&p0h;
            u2.y = *(unsigned*)&p1h;
            *(uint2*)(plane + (size_t)(m0 + r) * 512 + dnb + cc) = u2;
        }
    } else {
        #pragma unroll
        for (int t = 0; t < 16; t++) {
            const int r = warp * 16 + t;
            float4 v = *(float4*)&smf[r * EPI_STRIDE + cc];
            __half2 p0h = __floats2half2_rn(v.x, v.y);
            __half2 p1h = __floats2half2_rn(v.z, v.w);
            uint2 u2;
            u2.x = *(unsigned*)&p0h;
            u2.y = *(unsigned*)&p1h;
            *(uint2*)(plane + (size_t)(m0 + r) * 512 + dnb + cc) = u2;
        }
    }
}

// ---------------- scan (half2 vectorized: 2 lanes/thread) ----------------
__device__ __forceinline__ float2 h2f(const __half* p, size_t idx2) {
    __half2 h = *(const __half2*)(p + idx2 * 2);
    return __half22float2(h);
}

__global__ __launch_bounds__(256)
void scan_pass1(const float2* __restrict__ d_init2)
{
    const int gid   = blockIdx.x * blockDim.x + threadIdx.x;
    const int l2    = gid & (LANE2 - 1);
    const int chunk = gid >> 12;
    const int dir   = (l2 >> 7) & 1;
    const int s0    = chunk * TCHUNK;

    float2 d;
    if (s0 == 0) d = d_init2[l2];
    else {
        const int sp = s0 - 1;
        const int tp = dir ? (LSEQ - 1 - sp) : sp;
        d = h2f(g_u[1], (size_t)tp * LANE2 + l2);
    }

    float2 A1 = {1.f, 1.f}, B1 = {0.f, 0.f}, A2 = {1.f, 1.f}, B2 = {0.f, 0.f};
    #pragma unroll 4
    for (int i = 0; i < TCHUNK; i++) {
        const int s = s0 + i;
        const int t = dir ? (LSEQ - 1 - s) : s;
        const size_t b = (size_t)t * LANE2 + l2;
        float2 x1 = h2f(g_u[0], b);
        float2 x2 = h2f(g_u[1], b);
        float2 x3 = h2f(g_u[2], b);
        float2 f1 = h2f(g_u[3], b);
        float2 f2 = h2f(g_u[4], b);
        A1.x *= f1.x; A1.y *= f1.y;
        B1.x = f1.x * B1.x + (1.f - f1.x) * x1.x;
        B1.y = f1.y * B1.y + (1.f - f1.y) * x1.y;
        float tx = x3.x * d.x, ty = x3.y * d.y;
        A2.x *= f2.x; A2.y *= f2.y;
        B2.x = f2.x * B2.x + (1.f - f2.x) * tx;
        B2.y = f2.y * B2.y + (1.f - f2.y) * ty;
        d = x2;
    }
    const int o = chunk * LANE2 + l2;
    ((float2*)g_A1)[o] = A1; ((float2*)g_B1)[o] = B1;
    ((float2*)g_A2)[o] = A2; ((float2*)g_B2)[o] = B2;
}

__global__ __launch_bounds__(256)
void scan_pass2(const float2* __restrict__ c1_init2,
                const float2* __restrict__ c2_init2,
                float* __restrict__ out)
{
    const int l2 = blockIdx.x * blockDim.x + threadIdx.x;   // 0..4095
    float2 c1 = c1_init2[l2];
    float2 c2 = c2_init2[l2];
    for (int c = 0; c < NCHUNK; c++) {
        const int o = c * LANE2 + l2;
        ((float2*)g_c1in)[o] = c1;
        ((float2*)g_c2in)[o] = c2;
        float2 A1 = ((const float2*)g_A1)[o], B1 = ((const float2*)g_B1)[o];
        float2 A2 = ((const float2*)g_A2)[o], B2 = ((const float2*)g_B2)[o];
        c1.x = A1.x * c1.x + B1.x;  c1.y = A1.y * c1.y + B1.y;
        c2.x = A2.x * c2.x + B2.x;  c2.y = A2.y * c2.y + B2.y;
    }
    const size_t tail2 = (size_t)LSEQ * LANE2 * 2;          // in float2 units
    float2* out2 = (float2*)out;
    out2[tail2 + l2]         = c1;
    out2[tail2 + LANE2 + l2] = c2;
    const int dir = (l2 >> 7) & 1;
    const int tlast = dir ? 0 : (LSEQ - 1);
    out2[tail2 + 2 * LANE2 + l2] = h2f(g_u[1], (size_t)tlast * LANE2 + l2);
}

__global__ __launch_bounds__(256)
void scan_pass3(const float2* __restrict__ d_init2,
                float* __restrict__ out)
{
    const int gid   = blockIdx.x * blockDim.x + threadIdx.x;
    const int l2    = gid & (LANE2 - 1);
    const int chunk = gid >> 12;
    const int dir   = (l2 >> 7) & 1;
    const int s0    = chunk * TCHUNK;

    float2 d;
    if (s0 == 0) d = d_init2[l2];
    else {
        const int sp = s0 - 1;
        const int tp = dir ? (LSEQ - 1 - sp) : sp;
        d = h2f(g_u[1], (size_t)tp * LANE2 + l2);
    }

    const int o = chunk * LANE2 + l2;
    float2 c1 = ((const float2*)g_c1in)[o];
    float2 c2 = ((const float2*)g_c2in)[o];
    float2* out_c1 = (float2*)out;
    float2* out_c2 = out_c1 + (size_t)LSEQ * LANE2;

    #pragma unroll 4
    for (int i = 0; i < TCHUNK; i++) {
        const int s = s0 + i;
        const int t = dir ? (LSEQ - 1 - s) : s;
        const size_t b = (size_t)t * LANE2 + l2;
        float2 x1 = h2f(g_u[0], b);
        float2 x2 = h2f(g_u[1], b);
        float2 x3 = h2f(g_u[2], b);
        float2 f1 = h2f(g_u[3], b);
        float2 f2 = h2f(g_u[4], b);
        c1.x = (c1.x - x1.x) * f1.x + x1.x;
        c1.y = (c1.y - x1.y) * f1.y + x1.y;
        float tx = x3.x * d.x, ty = x3.y * d.y;
        c2.x = (c2.x - tx) * f2.x + tx;
        c2.y = (c2.y - ty) * f2.y + ty;
        d = x2;
        out_c1[b] = c1;
        out_c2[b] = c2;
    }
}

// ======================================================================
extern "C" void kernel_launch(void* const* d_in, const int* in_sizes, int n_in,
                              void* d_out, int out_size)
{
    const float* x    = (const float*)d_in[0];
    const float* w    = (const float*)d_in[1];
    const float* bias = (const float*)d_in[2];
    const float* c1i  = (const float*)d_in[3];
    const float* c2i  = (const float*)d_in[4];
    const float* di   = (const float*)d_in[5];
    float* out = (float*)d_out;

    static int attr_set = 0;
    if (!attr_set) {
        cudaFuncSetAttribute(gemm_mma, cudaFuncAttributeMaxDynamicSharedMemorySize, GEMM_SMEM);
        attr_set = 1;
    }

    split_x<<<8192, 256>>>((const float4*)x);
    prep_w<<<7680, 256>>>(w);
    gemm_mma<<<dim3(20, 256), 256, GEMM_SMEM>>>(bias);

    scan_pass1<<<(NCHUNK * LANE2) / 256, 256>>>((const float2*)di);
    scan_pass2<<<LANE2 / 256, 256>>>((const float2*)c1i, (const float2*)c2i, out);
    scan_pass3<<<(NCHUNK * LANE2) / 256, 256>>>((const float2*)di, out);
}